// round 4
// baseline (speedup 1.0000x reference)
#include <cuda_runtime.h>
#include <math.h>

#define MAXN 100000
#define C 32

// Static device scratch (no runtime allocation allowed)
__device__ float        g_deg [MAXN];
__device__ float        g_dinv[MAXN];
__device__ signed char  g_lbl [MAXN];             // label if masked else -1
__device__ float        g_p   [(size_t)MAXN * C]; // blended probabilities
__device__ float        g_H   [C * C];            // raw class-pair accumulator
__device__ float        g_cnt [C];                // masked count per class
__device__ unsigned     g_mflags;                 // mask dtype detection flags

// ---------------------------------------------------------------------------
// K0: init accumulators. deg starts at 1.0 (the self-loop weight).
// ---------------------------------------------------------------------------
__global__ void k0_init(int N) {
    int i = blockIdx.x * blockDim.x + threadIdx.x;
    if (i < N)    g_deg[i] = 1.0f;
    if (i < C*C)  g_H[i]   = 0.0f;
    if (i < C)    g_cnt[i] = 0.0f;
    if (i == 0)   g_mflags = 0u;
}

// ---------------------------------------------------------------------------
// Kd: mask dtype detection. Scan the first nwords 32-bit words (nwords = N/4,
// which is within bounds for every candidate dtype: uint8 buffer = N bytes =
// N/4 words). Flags: bit0 = not-int32(0/1), bit1 = not-float32(0.0/1.0),
// bit2 = not-bf16-pair.
// ---------------------------------------------------------------------------
__global__ void kd_detect(const unsigned* __restrict__ m, int nwords) {
    unsigned f = 0;
    int i = blockIdx.x * blockDim.x + threadIdx.x;
    if (i < nwords) {
        unsigned v = m[i];
        if (!(v == 0u || v == 1u))                                        f |= 1u;
        if (!(v == 0u || v == 0x3F800000u))                               f |= 2u;
        if (!(v == 0u || v == 0x00003F80u || v == 0x3F800000u ||
              v == 0x3F803F80u))                                          f |= 4u;
    }
    #pragma unroll
    for (int o = 16; o; o >>= 1) f |= __shfl_xor_sync(0xffffffffu, f, o);
    if ((threadIdx.x & 31) == 0 && f) atomicOr(&g_mflags, f);
}

__device__ __forceinline__ bool read_mask(const void* mv, int i) {
    unsigned fl = g_mflags;
    if (!(fl & 1u)) return ((const int*)mv)[i] != 0;                       // int32
    if (!(fl & 2u)) return ((const unsigned*)mv)[i] == 0x3F800000u;        // f32
    if (!(fl & 4u)) return ((const unsigned short*)mv)[i] != 0;            // bf16
    return ((const unsigned char*)mv)[i] != 0;                             // u8
}

// ---------------------------------------------------------------------------
// K1: degree accumulation over edges (segment_sum of w by row).
// ---------------------------------------------------------------------------
__global__ void k1_deg(const int* __restrict__ rows, const float* __restrict__ w, int E) {
    int e = blockIdx.x * blockDim.x + threadIdx.x;
    if (e < E) atomicAdd(&g_deg[rows[e]], w[e]);
}

// ---------------------------------------------------------------------------
// K2: per-node (one warp per node, lane = class):
//   p = masked ? y : softmax(inputs); dinv = rsqrt(deg); label; cnt;
//   self-loop contribution H[l][l] += dinv^2 (p = onehot on masked nodes).
// ---------------------------------------------------------------------------
__global__ void k2_node(const float* __restrict__ inp, const float* __restrict__ y,
                        const void* __restrict__ mask, int N) {
    int gw   = (blockIdx.x * blockDim.x + threadIdx.x) >> 5;
    int lane = threadIdx.x & 31;
    if (gw >= N) return;

    float x = inp[(size_t)gw * C + lane];
    float mx = x;
    #pragma unroll
    for (int o = 16; o; o >>= 1) mx = fmaxf(mx, __shfl_xor_sync(0xffffffffu, mx, o));
    float ex = __expf(x - mx);
    float s = ex;
    #pragma unroll
    for (int o = 16; o; o >>= 1) s += __shfl_xor_sync(0xffffffffu, s, o);
    float pv = ex / s;

    bool m = read_mask(mask, gw);
    int lbl = -1;
    if (m) {
        float yv = y[(size_t)gw * C + lane];
        pv = yv;
        unsigned b = __ballot_sync(0xffffffffu, yv == 1.0f);
        lbl = __ffs(b) - 1;
    }
    g_p[(size_t)gw * C + lane] = pv;

    if (lane == 0) {
        float d  = g_deg[gw];
        float di = d > 0.0f ? rsqrtf(d) : 0.0f;
        g_dinv[gw] = di;
        g_lbl[gw]  = (signed char)lbl;
        if (m) {
            atomicAdd(&g_cnt[lbl], 1.0f);
            atomicAdd(&g_H[lbl * C + lbl], di * di);   // self-loop edge
        }
    }
}

// ---------------------------------------------------------------------------
// K3: edge accumulation. H[lbl(row)][:] += val * p[col][:] for masked rows.
// Warp-private shared accumulators, shuffle-broadcast edge params, gathers
// issued in groups of 8 for MLP.
// ---------------------------------------------------------------------------
__global__ void k3_edges(const int* __restrict__ rows, const int* __restrict__ cols,
                         const float* __restrict__ w, int E) {
    __shared__ float acc[8 * C * C];   // 8 warps * 1024 floats = 32 KB
    int lane = threadIdx.x & 31;
    int wid  = threadIdx.x >> 5;
    float* myacc = acc + wid * (C * C);
    #pragma unroll
    for (int i = lane; i < C * C; i += 32) myacc[i] = 0.0f;
    __syncwarp();

    int gw = (blockIdx.x * blockDim.x + threadIdx.x) >> 5;
    int nw = (gridDim.x * blockDim.x) >> 5;

    for (int base = gw * 32; base < E; base += nw * 32) {
        int e = base + lane;
        bool v = (e < E);
        int   r  = v ? rows[e] : 0;
        int   cc0= v ? cols[e] : 0;
        float ww = v ? w[e]    : 0.0f;
        int   lb = v ? (int)g_lbl[r] : -1;
        float val= v ? g_dinv[r] * ww * g_dinv[cc0] : 0.0f;

        #pragma unroll
        for (int g = 0; g < 32; g += 8) {
            int   lbs[8]; int ccs[8]; float vvs[8]; float pv[8];
            #pragma unroll
            for (int k = 0; k < 8; k++) {
                lbs[k] = __shfl_sync(0xffffffffu, lb,  g + k);
                ccs[k] = __shfl_sync(0xffffffffu, cc0, g + k);
                vvs[k] = __shfl_sync(0xffffffffu, val, g + k);
            }
            #pragma unroll
            for (int k = 0; k < 8; k++)
                pv[k] = (lbs[k] >= 0) ? g_p[(size_t)ccs[k] * C + lane] : 0.0f;
            #pragma unroll
            for (int k = 0; k < 8; k++)
                if (lbs[k] >= 0)
                    myacc[lbs[k] * C + lane] += vvs[k] * pv[k];
        }
    }
    __syncthreads();

    for (int cell = threadIdx.x; cell < C * C; cell += blockDim.x) {
        float s = 0.0f;
        #pragma unroll
        for (int wv = 0; wv < 8; wv++) s += acc[wv * (C * C) + cell];
        atomicAdd(&g_H[cell], s);
    }
}

// ---------------------------------------------------------------------------
// K4: finalize. H /= cnt; NaN fixups; Sinkhorn with exact fixed-point /
// period-2 early exit (bit-identical to running all 3000 iterations).
// __syncthreads_or is ANY-nonzero, not bitwise-OR: one call per predicate.
// ---------------------------------------------------------------------------
__global__ void k4_final(float* __restrict__ out) {
    __shared__ float sm[C * 33];
    __shared__ float colsum[C];

    int j = threadIdx.x & 31;   // column (lane)
    int i = threadIdx.x >> 5;   // row (warp)

    float cnt = g_cnt[i];
    float h = g_H[i * C + j] / cnt;          // 0/0 -> NaN matches reference

    sm[i * 33 + j] = h;
    __syncthreads();
    float ht = sm[j * 33 + i];
    bool n1 = isnan(h);
    h = n1 ? ht : h;
    bool n2 = isnan(h);
    float h0 = n2 ? 0.0f : h;
    float rs = h0;
    int   nc = n2 ? 1 : 0;
    #pragma unroll
    for (int o = 16; o; o >>= 1) {
        rs += __shfl_xor_sync(0xffffffffu, rs, o);
        nc += __shfl_xor_sync(0xffffffffu, nc, o);
    }
    if (n2) h = (1.0f - rs) / (float)nc;
    __syncthreads();

    float prev1 = -1e30f, prev2 = -2e30f;
    for (int it = 0; it < 3000; it++) {
        sm[i * 33 + j] = h;
        __syncthreads();
        float cv = sm[j * 33 + i];
        #pragma unroll
        for (int o = 16; o; o >>= 1) cv += __shfl_xor_sync(0xffffffffu, cv, o);
        if (j == 0) colsum[i] = cv;
        __syncthreads();
        h = h / colsum[j];
        float rsum = h;
        #pragma unroll
        for (int o = 16; o; o >>= 1) rsum += __shfl_xor_sync(0xffffffffu, rsum, o);
        h = h / rsum;

        int any_ne1 = __syncthreads_or(h != prev1 ? 1 : 0);
        int any_ne2 = __syncthreads_or(h != prev2 ? 1 : 0);
        if (!any_ne1) break;                   // exact fixed point
        if (it >= 2 && !any_ne2) {             // exact period-2 cycle
            int rem = 2999 - it;
            if (rem & 1) h = prev1;
            break;
        }
        prev2 = prev1;
        prev1 = h;
    }

    out[i * C + j] = h;
}

// ---------------------------------------------------------------------------
extern "C" void kernel_launch(void* const* d_in, const int* in_sizes, int n_in,
                              void* d_out, int out_size) {
    const int*   ei   = (const int*)d_in[0];     // (2, E)
    const float* ew   = (const float*)d_in[1];   // (E,)
    const float* inp  = (const float*)d_in[2];   // (N, C)
    const float* y    = (const float*)d_in[3];   // (N, C)
    const void*  mask = d_in[4];                 // (N,) bool in unknown storage

    int E = in_sizes[0] / 2;
    int N = in_sizes[4];
    const int* rows = ei;
    const int* cols = ei + E;

    int nwords = N / 4;   // bounded by smallest candidate buffer (uint8: N bytes)

    k0_init  <<<(N + 255) / 256, 256>>>(N);
    kd_detect<<<(nwords + 255) / 256, 256>>>((const unsigned*)mask, nwords);
    k1_deg   <<<(E + 255) / 256, 256>>>(rows, ew, E);
    k2_node  <<<(N * 32 + 255) / 256, 256>>>(inp, y, mask, N);
    k3_edges <<<888, 256>>>(rows, cols, ew, E);
    k4_final <<<1, 1024>>>((float*)d_out);
}

// round 17
// speedup vs baseline: 2.1476x; 2.1476x over previous
#include <cuda_runtime.h>
#include <math.h>

#define MAXN 100000
#define C 32

// Static device scratch (no runtime allocation allowed)
__device__ float2       g_node[MAXN];             // {dinv, label(-1 if unmasked)}
__device__ float        g_deg [MAXN];
__device__ float        g_p   [(size_t)MAXN * C]; // softmax rows (unmasked nodes only)
__device__ float        g_H   [C * C];            // raw class-pair accumulator
__device__ float        g_cnt [C];                // masked count per class
__device__ unsigned     g_mflags;                 // mask dtype detection flags

// ---------------------------------------------------------------------------
// K0: init + mask dtype detection in one pass.
// Detection scans first N/4 32-bit words (in-bounds for every candidate dtype).
// flags: bit0 = not-int32(0/1), bit1 = not-f32(0/1.0), bit2 = not-bf16-pair.
// ---------------------------------------------------------------------------
__global__ void k0_init(const unsigned* __restrict__ m, int N, int nwords) {
    int i = blockIdx.x * blockDim.x + threadIdx.x;
    if (i < N)    g_deg[i] = 1.0f;       // self-loop weight
    if (i < C*C)  g_H[i]   = 0.0f;
    if (i < C)    g_cnt[i] = 0.0f;
    if (i == 0)   g_mflags = 0u;

    unsigned f = 0;
    if (i < nwords) {
        unsigned v = m[i];
        if (!(v == 0u || v == 1u))                                        f |= 1u;
        if (!(v == 0u || v == 0x3F800000u))                               f |= 2u;
        if (!(v == 0u || v == 0x00003F80u || v == 0x3F800000u ||
              v == 0x3F803F80u))                                          f |= 4u;
    }
    #pragma unroll
    for (int o = 16; o; o >>= 1) f |= __shfl_xor_sync(0xffffffffu, f, o);
    if ((threadIdx.x & 31) == 0 && f) atomicOr(&g_mflags, f);
}

__device__ __forceinline__ bool read_mask(const void* mv, int i) {
    unsigned fl = g_mflags;
    if (!(fl & 1u)) return ((const int*)mv)[i] != 0;                  // int32
    if (!(fl & 2u)) return ((const unsigned*)mv)[i] == 0x3F800000u;   // f32
    if (!(fl & 4u)) return ((const unsigned short*)mv)[i] != 0;       // bf16
    return ((const unsigned char*)mv)[i] != 0;                        // u8
}

// ---------------------------------------------------------------------------
// K1: degree accumulation (segment_sum of w by row). Spread REDs.
// ---------------------------------------------------------------------------
__global__ void k1_deg(const int* __restrict__ rows, const float* __restrict__ w, int E) {
    int e = blockIdx.x * blockDim.x + threadIdx.x;
    if (e < E) atomicAdd(&g_deg[rows[e]], w[e]);
}

// ---------------------------------------------------------------------------
// K2: thread-per-node. Register softmax over 32 classes (no shuffles, no
// cross-lane chains). Writes p only for unmasked nodes; packs {dinv,lbl};
// block-aggregates cnt / H-diag (self-loop) atomics.
// ---------------------------------------------------------------------------
__global__ void k2_node(const float* __restrict__ inp, const float* __restrict__ y,
                        const void* __restrict__ mask, int N) {
    __shared__ float s_cnt[C];
    __shared__ float s_hd [C];
    if (threadIdx.x < C) { s_cnt[threadIdx.x] = 0.0f; s_hd[threadIdx.x] = 0.0f; }
    __syncthreads();

    int i = blockIdx.x * blockDim.x + threadIdx.x;
    if (i < N) {
        float d  = g_deg[i];
        float di = d > 0.0f ? rsqrtf(d) : 0.0f;
        bool  m  = read_mask(mask, i);

        if (m) {
            // label from one-hot y row
            const float4* y4 = (const float4*)y + (size_t)i * 8;
            int lbl = 0;
            #pragma unroll
            for (int k = 0; k < 8; k++) {
                float4 v = y4[k];
                if (v.x == 1.0f) lbl = 4*k;
                if (v.y == 1.0f) lbl = 4*k+1;
                if (v.z == 1.0f) lbl = 4*k+2;
                if (v.w == 1.0f) lbl = 4*k+3;
            }
            g_node[i] = make_float2(di, (float)lbl);
            atomicAdd(&s_cnt[lbl], 1.0f);
            atomicAdd(&s_hd [lbl], di * di);       // self-loop: p=onehot
        } else {
            // register softmax
            const float4* in4 = (const float4*)inp + (size_t)i * 8;
            float v[32];
            #pragma unroll
            for (int k = 0; k < 8; k++) {
                float4 t = in4[k];
                v[4*k] = t.x; v[4*k+1] = t.y; v[4*k+2] = t.z; v[4*k+3] = t.w;
            }
            float mx = v[0];
            #pragma unroll
            for (int k = 1; k < 32; k++) mx = fmaxf(mx, v[k]);
            float s = 0.0f;
            #pragma unroll
            for (int k = 0; k < 32; k++) { v[k] = __expf(v[k] - mx); s += v[k]; }
            float inv = 1.0f / s;
            float4* p4 = (float4*)g_p + (size_t)i * 8;
            #pragma unroll
            for (int k = 0; k < 8; k++) {
                float4 t;
                t.x = v[4*k]*inv; t.y = v[4*k+1]*inv;
                t.z = v[4*k+2]*inv; t.w = v[4*k+3]*inv;
                p4[k] = t;
            }
            g_node[i] = make_float2(di, -1.0f);
        }
    }
    __syncthreads();
    if (threadIdx.x < C) {
        float c = s_cnt[threadIdx.x], hd = s_hd[threadIdx.x];
        if (c  != 0.0f) atomicAdd(&g_cnt[threadIdx.x], c);
        if (hd != 0.0f) atomicAdd(&g_H[threadIdx.x * C + threadIdx.x], hd);
    }
}

// ---------------------------------------------------------------------------
// K3: edge accumulation, split by col type.
//   masked row -> masked col:    scalar H[lb][lc] += val  (shared atomic)
//   masked row -> unmasked col:  H[lb][:] += val * p[col][:] (warp gather,
//                                per-warp private accumulator, pairwise MLP)
// ---------------------------------------------------------------------------
__global__ void k3_edges(const int* __restrict__ rows, const int* __restrict__ cols,
                         const float* __restrict__ w, int E) {
    __shared__ float wacc[8][C * C];   // per-warp accumulators (32 KB)
    __shared__ float mmacc[C * C];     // block-shared mm histogram (4 KB)
    int lane = threadIdx.x & 31;
    int wid  = threadIdx.x >> 5;
    float* myacc = wacc[wid];
    #pragma unroll
    for (int t = lane; t < C * C; t += 32) myacc[t] = 0.0f;
    for (int t = threadIdx.x; t < C * C; t += blockDim.x) mmacc[t] = 0.0f;
    __syncthreads();

    int gw = (blockIdx.x * blockDim.x + threadIdx.x) >> 5;
    int nw = (gridDim.x * blockDim.x) >> 5;

    for (int base = gw * 32; base < E; base += nw * 32) {
        int e = base + lane;
        bool valid = (e < E);
        int   r  = valid ? rows[e] : 0;
        int   c  = valid ? cols[e] : 0;
        float ww = valid ? w[e]    : 0.0f;

        float2 nr = valid ? g_node[r] : make_float2(0.0f, -1.0f);
        int lb = (int)nr.y;
        bool rm = valid && (lb >= 0);

        float2 nc = rm ? g_node[c] : make_float2(0.0f, -1.0f);
        float val = nr.x * ww * nc.x;
        int lc = (int)nc.y;

        if (rm && lc >= 0)
            atomicAdd(&mmacc[lb * C + lc], val);     // spread banks

        unsigned mu = __ballot_sync(0xffffffffu, rm && lc < 0);
        while (mu) {
            int s0 = __ffs(mu) - 1; mu &= mu - 1;
            int s1 = mu ? (__ffs(mu) - 1) : -1; if (s1 >= 0) mu &= mu - 1;

            int   c0 = __shfl_sync(0xffffffffu, c,   s0);
            float v0 = __shfl_sync(0xffffffffu, val, s0);
            int   l0 = __shfl_sync(0xffffffffu, lb,  s0);
            int   c1 = __shfl_sync(0xffffffffu, c,   s1 >= 0 ? s1 : s0);
            float v1 = __shfl_sync(0xffffffffu, val, s1 >= 0 ? s1 : s0);
            int   l1 = __shfl_sync(0xffffffffu, lb,  s1 >= 0 ? s1 : s0);

            float p0 = g_p[(size_t)c0 * C + lane];
            float p1 = (s1 >= 0) ? g_p[(size_t)c1 * C + lane] : 0.0f;

            myacc[l0 * C + lane] += v0 * p0;
            if (s1 >= 0) myacc[l1 * C + lane] += v1 * p1;
        }
    }
    __syncthreads();

    for (int cell = threadIdx.x; cell < C * C; cell += blockDim.x) {
        float s = mmacc[cell];
        #pragma unroll
        for (int wv = 0; wv < 8; wv++) s += wacc[wv][cell];
        if (s != 0.0f) atomicAdd(&g_H[cell], s);
    }
}

// ---------------------------------------------------------------------------
// K4: H /= cnt; NaN fixups; Sinkhorn (col-norm then row-norm).
// Exit: every 4 iterations compare to the state 4 iterations ago; if
// max abs diff < 1e-9, replay (2999-it)&3 extra iterations to land on the
// reference's parity for any period in {1,2,4}. Error bound 1e-9 << 1e-3.
// If a longer-period cycle exists, 'moving' stays 1 and we fall back to the
// full 3000 iterations (exactly reference behavior) — the exit is fail-safe.
// ---------------------------------------------------------------------------
__device__ __forceinline__ void sinkhorn_iter(float& h, float* sm, float* colsum,
                                              int i, int j) {
    sm[i * 33 + j] = h;
    __syncthreads();
    float cv = sm[j * 33 + i];                  // warp i reduces column i
    #pragma unroll
    for (int o = 16; o; o >>= 1) cv += __shfl_xor_sync(0xffffffffu, cv, o);
    if (j == 0) colsum[i] = cv;
    __syncthreads();
    h = h / colsum[j];
    float rsum = h;
    #pragma unroll
    for (int o = 16; o; o >>= 1) rsum += __shfl_xor_sync(0xffffffffu, rsum, o);
    h = h / rsum;
}

__global__ void k4_final(float* __restrict__ out) {
    __shared__ float sm[C * 33];
    __shared__ float colsum[C];

    int j = threadIdx.x & 31;   // column (lane)
    int i = threadIdx.x >> 5;   // row (warp)

    float cnt = g_cnt[i];
    float h = g_H[i * C + j] / cnt;          // 0/0 -> NaN matches reference

    // NaN fixups (identity when all classes populated)
    sm[i * 33 + j] = h;
    __syncthreads();
    float ht = sm[j * 33 + i];
    h = isnan(h) ? ht : h;
    bool n2 = isnan(h);
    float h0 = n2 ? 0.0f : h;
    float rs = h0;
    int   nc = n2 ? 1 : 0;
    #pragma unroll
    for (int o = 16; o; o >>= 1) {
        rs += __shfl_xor_sync(0xffffffffu, rs, o);
        nc += __shfl_xor_sync(0xffffffffu, nc, o);
    }
    if (n2) h = (1.0f - rs) / (float)nc;
    __syncthreads();

    float saved = h;                          // state after 0 iterations
    for (int it = 0; it < 3000; it++) {
        sinkhorn_iter(h, sm, colsum, i, j);
        if ((it & 3) == 3) {
            int moving = __syncthreads_or(fabsf(h - saved) >= 1e-9f ? 1 : 0);
            if (!moving) {
                int rem = (2999 - it) & 3;    // parity alignment for period|4
                for (int q = 0; q < rem; q++) sinkhorn_iter(h, sm, colsum, i, j);
                break;
            }
            saved = h;
        }
    }

    out[i * C + j] = h;
}

// ---------------------------------------------------------------------------
extern "C" void kernel_launch(void* const* d_in, const int* in_sizes, int n_in,
                              void* d_out, int out_size) {
    const int*   ei   = (const int*)d_in[0];     // (2, E)
    const float* ew   = (const float*)d_in[1];   // (E,)
    const float* inp  = (const float*)d_in[2];   // (N, C)
    const float* y    = (const float*)d_in[3];   // (N, C)
    const void*  mask = d_in[4];                 // (N,) bool, storage detected

    int E = in_sizes[0] / 2;
    int N = in_sizes[4];
    const int* rows = ei;
    const int* cols = ei + E;
    int nwords = N / 4;

    k0_init <<<(N + 255) / 256, 256>>>((const unsigned*)mask, N, nwords);
    k1_deg  <<<(E + 255) / 256, 256>>>(rows, ew, E);
    k2_node <<<(N + 255) / 256, 256>>>(inp, y, mask, N);
    k3_edges<<<888, 256>>>(rows, cols, ew, E);
    k4_final<<<1, 1024>>>((float*)d_out);
}